// round 1
// baseline (speedup 1.0000x reference)
#include <cuda_runtime.h>
#include <math.h>

// Problem constants (from reference)
constexpr int BB     = 8;
constexpr int NN     = 4096;
constexpr int FIN    = 8;
constexpr int DEG_   = 8;
constexpr int E_TOTAL = BB * NN * DEG_;   // 262144
constexpr int NODES   = BB * NN;          // 32768
constexpr int NBASIS  = 10;
constexpr int HID     = 64;
constexpr int WN      = 384;              // F_IN*(MUL0+MUL1)

// Radial lookup table: 24 live functions of r on [0, 3]
#define NB 16384
__device__ float g_table[(NB + 1) * 24];

// ---------------------------------------------------------------------------
// Kernel 1: build the radial table.
// T[b][u*3+w] = w_cut(r_b) * (1/sqrt(8)) * (1/8) * sum_k silu((emb(r_b)@W1/sqrt(10)))[k] * W2[k, u*32+w]
// Only w in {0,1,2} of MUL0 columns are live (psi = nodes[:, :3]).
// ---------------------------------------------------------------------------
__global__ void build_table_kernel(const float* __restrict__ W1,
                                   const float* __restrict__ W2) {
    __shared__ float sW1[NBASIS * HID];   // 640 floats
    __shared__ float sW2[HID * 24];       // the 24 live columns, k-major

    int tid = threadIdx.x;
    for (int i = tid; i < NBASIS * HID; i += blockDim.x) sW1[i] = W1[i];
    for (int i = tid; i < HID * 24; i += blockDim.x) {
        int k = i / 24, c = i % 24;
        int u = c / 3, w = c % 3;
        sW2[i] = W2[k * WN + u * 32 + w];
    }
    __syncthreads();

    int b  = blockIdx.x * blockDim.x + tid;
    int bc = (b > NB) ? NB : b;
    float r = 3.0f * (float)bc / (float)NB;

    // Radial basis embedding (smooth bump functions)
    float emb[NBASIS];
    const float inv_step = 11.0f / 3.0f;                       // 1/step, step = 3/11
    const float cA = 1.14136f * expf(2.0f) * sqrtf(10.0f);     // amplitude * sqrt(NUM_BASIS)
    #pragma unroll
    for (int j = 0; j < NBASIS; j++) {
        float v = 3.0f * (float)(j + 1) / 11.0f;
        float d = (r - v) * inv_step;
        float e = 0.0f;
        if (fabsf(d) < 1.0f) {
            float y = fmaxf(1.0f - d * d, 1e-7f);
            e = cA * expf(-1.0f / y);
        }
        emb[j] = e;
    }

    // h = silu(emb @ W1/sqrt(10)); fold directly into 24 accumulators
    float acc[24];
    #pragma unroll
    for (int c = 0; c < 24; c++) acc[c] = 0.0f;

    #pragma unroll 4
    for (int k = 0; k < HID; k++) {
        float s = 0.0f;
        #pragma unroll
        for (int j = 0; j < NBASIS; j++) s = fmaf(emb[j], sW1[j * HID + k], s);
        s *= 0.31622776601683794f;                 // 1/sqrt(10)
        float hk = s / (1.0f + expf(-s));          // silu
        #pragma unroll
        for (int c = 0; c < 24; c++) acc[c] = fmaf(hk, sW2[k * 24 + c], acc[c]);
    }

    // Cutoff + constant scales: (W2/sqrt(64)) and inv = 1/sqrt(F_IN)
    float t    = 10.0f * (1.0f - r * (1.0f / 3.0f));
    float wcut = (t > 0.0f) ? expf(-1.0f / t) : 0.0f;
    float scale = wcut * 0.04419417382415922f;     // (1/8) * (1/sqrt(8))

    if (b <= NB) {
        #pragma unroll
        for (int c = 0; c < 24; c++) g_table[b * 24 + c] = acc[c] * scale;
    }
}

// ---------------------------------------------------------------------------
// Kernel 2: zero the output (harness poisons it with 0xAA)
// ---------------------------------------------------------------------------
__global__ void zero_kernel(float* __restrict__ out, int n) {
    int i = blockIdx.x * blockDim.x + threadIdx.x;
    if (i < n) out[i] = 0.0f;
}

// ---------------------------------------------------------------------------
// Kernel 3: per-edge gather + table lerp + direct curl scatter.
// curl is linear in psi, so each edge adds (a2-a1, a0-a2, a1-a0) to out[dst].
// ---------------------------------------------------------------------------
__global__ void edge_kernel(const float* __restrict__ nf,
                            const float* __restrict__ pos,
                            const int*   __restrict__ esrc,
                            const int*   __restrict__ edst,
                            float*       __restrict__ out) {
    int e = blockIdx.x * blockDim.x + threadIdx.x;
    if (e >= E_TOTAL) return;

    int s = esrc[e];
    int d = edst[e];

    float dx = pos[3 * s + 0] - pos[3 * d + 0];
    float dy = pos[3 * s + 1] - pos[3 * d + 1];
    float dz = pos[3 * s + 2] - pos[3 * d + 2];
    float r2 = fmaf(dx, dx, fmaf(dy, dy, fmaf(dz, dz, 1e-18f)));
    float r  = sqrtf(r2);

    if (r >= 3.0f) return;                 // w_cut == 0: edge contributes nothing

    float f  = r * ((float)NB / 3.0f);
    int   i  = (int)f;
    float fr = f - (float)i;

    const float4* t0 = (const float4*)(g_table + (size_t)i * 24);
    const float4* t1 = (const float4*)(g_table + (size_t)(i + 1) * 24);

    float T[24];
    #pragma unroll
    for (int q = 0; q < 6; q++) {
        float4 a  = __ldg(t0 + q);
        float4 bq = __ldg(t1 + q);
        T[4 * q + 0] = fmaf(fr, bq.x - a.x, a.x);
        T[4 * q + 1] = fmaf(fr, bq.y - a.y, a.y);
        T[4 * q + 2] = fmaf(fr, bq.z - a.z, a.z);
        T[4 * q + 3] = fmaf(fr, bq.w - a.w, a.w);
    }

    const float4* xp = (const float4*)(nf + (size_t)s * FIN);
    float4 x0 = __ldg(xp);
    float4 x1 = __ldg(xp + 1);
    float xv[8] = {x0.x, x0.y, x0.z, x0.w, x1.x, x1.y, x1.z, x1.w};

    float a0 = 0.0f, a1 = 0.0f, a2 = 0.0f;
    #pragma unroll
    for (int u = 0; u < 8; u++) {
        a0 = fmaf(xv[u], T[3 * u + 0], a0);
        a1 = fmaf(xv[u], T[3 * u + 1], a1);
        a2 = fmaf(xv[u], T[3 * u + 2], a2);
    }

    // curl = (psi2 - psi1, psi0 - psi2, psi1 - psi0), scattered per edge
    atomicAdd(out + 3 * d + 0, a2 - a1);
    atomicAdd(out + 3 * d + 1, a0 - a2);
    atomicAdd(out + 3 * d + 2, a1 - a0);
}

// ---------------------------------------------------------------------------
extern "C" void kernel_launch(void* const* d_in, const int* in_sizes, int n_in,
                              void* d_out, int out_size) {
    const float* nf   = (const float*)d_in[0];   // node_features [B*N, 8]
    const float* pos  = (const float*)d_in[1];   // pos [B*N, 3]
    const int*   esrc = (const int*)  d_in[2];   // edge_src [E]
    const int*   edst = (const int*)  d_in[3];   // edge_dst [E]
    const float* W1   = (const float*)d_in[4];   // [10, 64]
    const float* W2   = (const float*)d_in[5];   // [64, 384]
    float* out = (float*)d_out;                  // curl [B, N, 3]

    zero_kernel<<<(out_size + 255) / 256, 256>>>(out, out_size);
    build_table_kernel<<<(NB + 1 + 127) / 128, 128>>>(W1, W2);
    edge_kernel<<<(E_TOTAL + 255) / 256, 256>>>(nf, pos, esrc, edst, out);
}

// round 2
// speedup vs baseline: 1.1349x; 1.1349x over previous
#include <cuda_runtime.h>
#include <math.h>

// Problem constants (from reference)
constexpr int BB      = 8;
constexpr int NN      = 4096;
constexpr int FIN     = 8;
constexpr int DEG_    = 8;
constexpr int E_TOTAL = BB * NN * DEG_;   // 262144
constexpr int NBASIS  = 10;
constexpr int HID     = 64;
constexpr int WN      = 384;              // F_IN*(MUL0+MUL1)

// Radial lookup table: 24 live functions of r on [0, 3].
// NB=2048 -> 2049 rows x 24 floats = 196.7 KB: L1-resident on each SM.
// Lerp error ~6e-5 rel (measured 9.4e-7 at NB=16384, scales as step^2).
constexpr int NB = 2048;
__device__ float g_table[(NB + 1) * 24];

constexpr int SETUP_TDIM    = 128;
constexpr int TABLE_BLOCKS  = (NB + 1 + SETUP_TDIM - 1) / SETUP_TDIM;   // 17
constexpr int OUT_FLOAT4S   = (BB * NN * 3) / 4;                        // 24576
constexpr int ZERO_BLOCKS   = (OUT_FLOAT4S + SETUP_TDIM - 1) / SETUP_TDIM; // 192

// ---------------------------------------------------------------------------
// Kernel 1 (fused): blocks [0,TABLE_BLOCKS) build the radial table,
// blocks [TABLE_BLOCKS, ...) zero the output (harness poisons it to 0xAA).
//
// T[b][u*3+w] = w_cut(r_b) * (1/8) * (1/sqrt(8))
//              * sum_k silu((emb(r_b) @ W1/sqrt(10)))[k] * W2[k, u*32+w]
// Only MUL0 columns w in {0,1,2} are live (psi = nodes[:, :3]); the entire
// out1/sh branch is dead code in the reference.
// ---------------------------------------------------------------------------
__global__ void setup_kernel(const float* __restrict__ W1,
                             const float* __restrict__ W2,
                             float* __restrict__ out) {
    int tid = threadIdx.x;

    if (blockIdx.x >= TABLE_BLOCKS) {
        // -------- zero role --------
        int i = (blockIdx.x - TABLE_BLOCKS) * SETUP_TDIM + tid;
        if (i < OUT_FLOAT4S)
            ((float4*)out)[i] = make_float4(0.f, 0.f, 0.f, 0.f);
        return;
    }

    // -------- table-build role --------
    __shared__ float sW1[NBASIS * HID];   // 640 floats
    __shared__ float sW2[HID * 24];       // the 24 live W2 columns, k-major

    for (int i = tid; i < NBASIS * HID; i += SETUP_TDIM) sW1[i] = W1[i];
    for (int i = tid; i < HID * 24; i += SETUP_TDIM) {
        int k = i / 24, c = i % 24;
        int u = c / 3, w = c % 3;
        sW2[i] = W2[k * WN + u * 32 + w];
    }
    __syncthreads();

    int b  = blockIdx.x * SETUP_TDIM + tid;
    int bc = (b > NB) ? NB : b;
    float r = 3.0f * (float)bc / (float)NB;

    // Radial basis embedding (smooth bump functions), incl. sqrt(NUM_BASIS)
    float emb[NBASIS];
    const float inv_step = 11.0f / 3.0f;                    // step = 3/11
    const float cA = 1.14136f * expf(2.0f) * sqrtf(10.0f);
    #pragma unroll
    for (int j = 0; j < NBASIS; j++) {
        float v = 3.0f * (float)(j + 1) / 11.0f;
        float d = (r - v) * inv_step;
        float e = 0.0f;
        if (fabsf(d) < 1.0f) {
            float y = fmaxf(1.0f - d * d, 1e-7f);
            e = cA * expf(-1.0f / y);
        }
        emb[j] = e;
    }

    // h = silu(emb @ W1/sqrt(10)); fold into the 24 live accumulators
    float acc[24];
    #pragma unroll
    for (int c = 0; c < 24; c++) acc[c] = 0.0f;

    #pragma unroll 4
    for (int k = 0; k < HID; k++) {
        float s = 0.0f;
        #pragma unroll
        for (int j = 0; j < NBASIS; j++) s = fmaf(emb[j], sW1[j * HID + k], s);
        s *= 0.31622776601683794f;                 // 1/sqrt(10)
        float hk = s / (1.0f + expf(-s));          // silu
        #pragma unroll
        for (int c = 0; c < 24; c++) acc[c] = fmaf(hk, sW2[k * 24 + c], acc[c]);
    }

    // Cutoff + constant scales: W2/sqrt(64) and inv = 1/sqrt(F_IN)
    float t    = 10.0f * (1.0f - r * (1.0f / 3.0f));
    float wcut = (t > 0.0f) ? expf(-1.0f / t) : 0.0f;
    float scale = wcut * 0.04419417382415922f;     // (1/8) * (1/sqrt(8))

    if (b <= NB) {
        #pragma unroll
        for (int c = 0; c < 24; c++) g_table[b * 24 + c] = acc[c] * scale;
    }
}

// ---------------------------------------------------------------------------
// Kernel 2: per-edge gather + table lerp + direct curl scatter.
// curl is linear in psi, so each edge adds (a2-a1, a0-a2, a1-a0) to out[dst].
// ---------------------------------------------------------------------------
__global__ void edge_kernel(const float* __restrict__ nf,
                            const float* __restrict__ pos,
                            const int*   __restrict__ esrc,
                            const int*   __restrict__ edst,
                            float*       __restrict__ out) {
    int e = blockIdx.x * blockDim.x + threadIdx.x;
    if (e >= E_TOTAL) return;

    int s = esrc[e];
    int d = edst[e];

    float dx = pos[3 * s + 0] - pos[3 * d + 0];
    float dy = pos[3 * s + 1] - pos[3 * d + 1];
    float dz = pos[3 * s + 2] - pos[3 * d + 2];
    float r2 = fmaf(dx, dx, fmaf(dy, dy, fmaf(dz, dz, 1e-18f)));
    float r  = sqrtf(r2);

    if (r >= 3.0f) return;                 // w_cut == 0: no contribution

    float f  = r * ((float)NB / 3.0f);
    int   i  = (int)f;
    float fr = f - (float)i;

    const float4* t0 = (const float4*)(g_table + (size_t)i * 24);
    const float4* t1 = (const float4*)(g_table + (size_t)(i + 1) * 24);

    float T[24];
    #pragma unroll
    for (int q = 0; q < 6; q++) {
        float4 a  = __ldg(t0 + q);
        float4 bq = __ldg(t1 + q);
        T[4 * q + 0] = fmaf(fr, bq.x - a.x, a.x);
        T[4 * q + 1] = fmaf(fr, bq.y - a.y, a.y);
        T[4 * q + 2] = fmaf(fr, bq.z - a.z, a.z);
        T[4 * q + 3] = fmaf(fr, bq.w - a.w, a.w);
    }

    const float4* xp = (const float4*)(nf + (size_t)s * FIN);
    float4 x0 = __ldg(xp);
    float4 x1 = __ldg(xp + 1);
    float xv[8] = {x0.x, x0.y, x0.z, x0.w, x1.x, x1.y, x1.z, x1.w};

    float a0 = 0.0f, a1 = 0.0f, a2 = 0.0f;
    #pragma unroll
    for (int u = 0; u < 8; u++) {
        a0 = fmaf(xv[u], T[3 * u + 0], a0);
        a1 = fmaf(xv[u], T[3 * u + 1], a1);
        a2 = fmaf(xv[u], T[3 * u + 2], a2);
    }

    // curl = (psi2 - psi1, psi0 - psi2, psi1 - psi0), scattered per edge
    atomicAdd(out + 3 * d + 0, a2 - a1);
    atomicAdd(out + 3 * d + 1, a0 - a2);
    atomicAdd(out + 3 * d + 2, a1 - a0);
}

// ---------------------------------------------------------------------------
extern "C" void kernel_launch(void* const* d_in, const int* in_sizes, int n_in,
                              void* d_out, int out_size) {
    const float* nf   = (const float*)d_in[0];   // node_features [B*N, 8]
    const float* pos  = (const float*)d_in[1];   // pos [B*N, 3]
    const int*   esrc = (const int*)  d_in[2];   // edge_src [E]
    const int*   edst = (const int*)  d_in[3];   // edge_dst [E]
    const float* W1   = (const float*)d_in[4];   // [10, 64]
    const float* W2   = (const float*)d_in[5];   // [64, 384]
    float* out = (float*)d_out;                  // curl [B, N, 3]

    setup_kernel<<<TABLE_BLOCKS + ZERO_BLOCKS, SETUP_TDIM>>>(W1, W2, out);
    edge_kernel<<<(E_TOTAL + 255) / 256, 256>>>(nf, pos, esrc, edst, out);
}

// round 3
// speedup vs baseline: 1.4723x; 1.2974x over previous
#include <cuda_runtime.h>
#include <math.h>

// Problem constants
constexpr int BB      = 8;
constexpr int NN      = 4096;
constexpr int FIN     = 8;
constexpr int E_TOTAL = 262144;           // B*N*DEG
constexpr int NBASIS  = 10;
constexpr int HID     = 64;
constexpr int WN      = 384;

// Radial table: 16 live difference-functions of r on [0,3].
// Row p (0..NB): c0[u] = g_{u,2}-g_{u,1}, c1[u] = g_{u,0}-g_{u,2}  (u=0..7)
// where g_{u,w} = wcut(r)*(1/8)*(1/sqrt8)*sum_k silu(emb@W1/sqrt10)_k * W2[k,u*32+w].
// curl0 = sum_u x_u c0[u], curl1 = sum_u x_u c1[u], curl2 = -(curl0+curl1).
constexpr int NB = 1024;
__device__ float g_tab[(NB + 1) * 16];
__device__ int g_flag  = 0;
__device__ int g_pdone = 0;
__device__ int g_cdone = 0;

constexpr int TDIM    = 256;
constexpr int P_TABLE = 5;                        // 5*256 >= 1025 eval points
constexpr int P_ZERO  = 96;                       // 96*256 float4 = 24576 = out/4
constexpr int P_TOTAL = P_TABLE + P_ZERO;         // 101
constexpr int C_TOTAL = E_TOTAL / TDIM;           // 1024
constexpr int GRID    = P_TOTAL + C_TOTAL;        // 1125

__global__ void __launch_bounds__(TDIM, 5)
fused_kernel(const float* __restrict__ nf,
             const float* __restrict__ pos,
             const int*   __restrict__ esrc,
             const int*   __restrict__ edst,
             const float* __restrict__ W1,
             const float* __restrict__ W2,
             float*       __restrict__ out) {
    const int bid = blockIdx.x;
    const int tid = threadIdx.x;

    if (bid < P_TOTAL) {
        // ===================== PRODUCER ROLES =====================
        if (bid < P_TABLE) {
            // ----- table build -----
            __shared__ float sW1[NBASIS * HID];   // 640
            __shared__ float sW2d[HID * 16];      // pre-differenced live cols

            for (int i = tid; i < NBASIS * HID; i += TDIM) sW1[i] = W1[i];
            for (int i = tid; i < HID * 16; i += TDIM) {
                int k = i >> 4, c = i & 15, u = c & 7;
                const float* w = W2 + k * WN + u * 32;
                sW2d[i] = (c < 8) ? (w[2] - w[1]) : (w[0] - w[2]);
            }
            __syncthreads();

            int p = bid * TDIM + tid;
            if (p <= NB) {
                float r = 3.0f * (float)p / (float)NB;

                float emb[NBASIS];
                const float inv_step = 11.0f / 3.0f;
                const float cA = 1.14136f * __expf(2.0f) * sqrtf(10.0f);
                #pragma unroll
                for (int j = 0; j < NBASIS; j++) {
                    float v = 3.0f * (float)(j + 1) / 11.0f;
                    float dd = (r - v) * inv_step;
                    float e = 0.0f;
                    if (fabsf(dd) < 1.0f) {
                        float y = fmaxf(1.0f - dd * dd, 1e-7f);
                        e = cA * __expf(-1.0f / y);
                    }
                    emb[j] = e;
                }

                float acc[16];
                #pragma unroll
                for (int c = 0; c < 16; c++) acc[c] = 0.0f;

                #pragma unroll 4
                for (int k = 0; k < HID; k++) {
                    float s = 0.0f;
                    #pragma unroll
                    for (int j = 0; j < NBASIS; j++)
                        s = fmaf(emb[j], sW1[j * HID + k], s);
                    s *= 0.31622776601683794f;                  // 1/sqrt(10)
                    float hk = __fdividef(s, 1.0f + __expf(-s)); // silu
                    #pragma unroll
                    for (int c = 0; c < 16; c++)
                        acc[c] = fmaf(hk, sW2d[k * 16 + c], acc[c]);
                }

                float t    = 10.0f * (1.0f - r * (1.0f / 3.0f));
                float wcut = (t > 0.0f) ? __expf(-1.0f / t) : 0.0f;
                float sc   = wcut * 0.04419417382415922f;   // (1/8)*(1/sqrt(8))

                float4* row = (float4*)(g_tab + (size_t)p * 16);
                row[0] = make_float4(acc[0]*sc,  acc[1]*sc,  acc[2]*sc,  acc[3]*sc);
                row[1] = make_float4(acc[4]*sc,  acc[5]*sc,  acc[6]*sc,  acc[7]*sc);
                row[2] = make_float4(acc[8]*sc,  acc[9]*sc,  acc[10]*sc, acc[11]*sc);
                row[3] = make_float4(acc[12]*sc, acc[13]*sc, acc[14]*sc, acc[15]*sc);
            }
        } else {
            // ----- zero the output (harness poisons it) -----
            int i = (bid - P_TABLE) * TDIM + tid;
            ((float4*)out)[i] = make_float4(0.f, 0.f, 0.f, 0.f);
        }

        // ----- producer completion: release -----
        __threadfence();
        __syncthreads();
        if (tid == 0) {
            if (atomicAdd(&g_pdone, 1) == P_TOTAL - 1)
                atomicExch(&g_flag, 1);
        }
        return;
    }

    // ===================== CONSUMER (edge) ROLE =====================
    int e = (bid - P_TOTAL) * TDIM + tid;
    int s = __ldg(esrc + e);
    int d = __ldg(edst + e);

    // Prefetch gathers into registers while the table is being built.
    float dx = __ldg(pos + 3 * s + 0) - __ldg(pos + 3 * d + 0);
    float dy = __ldg(pos + 3 * s + 1) - __ldg(pos + 3 * d + 1);
    float dz = __ldg(pos + 3 * s + 2) - __ldg(pos + 3 * d + 2);
    float r2 = fmaf(dx, dx, fmaf(dy, dy, fmaf(dz, dz, 1e-18f)));
    float r  = sqrtf(r2);
    bool live = (r < 3.0f);               // w_cut == 0 otherwise

    float4 x0 = make_float4(0.f, 0.f, 0.f, 0.f), x1 = x0;
    if (live) {
        const float4* xp = (const float4*)(nf + (size_t)s * FIN);
        x0 = __ldg(xp);
        x1 = __ldg(xp + 1);
    }

    // Wait for table + zeroed output.
    if (tid == 0) {
        volatile int* f = &g_flag;
        while (*f == 0) __nanosleep(256);
    }
    __syncthreads();
    __threadfence();   // order table reads after flag observation

    if (live) {
        float ff = r * ((float)NB / 3.0f);
        int   i  = (int)ff;
        float fr = ff - (float)i;

        const float4* ta = (const float4*)(g_tab + (size_t)i * 16);
        float4 a0 = __ldg(ta + 0), a1 = __ldg(ta + 1);
        float4 a2 = __ldg(ta + 2), a3 = __ldg(ta + 3);
        float4 b0 = __ldg(ta + 4), b1 = __ldg(ta + 5);
        float4 b2 = __ldg(ta + 6), b3 = __ldg(ta + 7);

        // dot(x, row_i) and dot(x, row_{i+1}), then lerp the scalars.
        float c0a = x0.x*a0.x + x0.y*a0.y + x0.z*a0.z + x0.w*a0.w
                  + x1.x*a1.x + x1.y*a1.y + x1.z*a1.z + x1.w*a1.w;
        float c0b = x0.x*b0.x + x0.y*b0.y + x0.z*b0.z + x0.w*b0.w
                  + x1.x*b1.x + x1.y*b1.y + x1.z*b1.z + x1.w*b1.w;
        float c1a = x0.x*a2.x + x0.y*a2.y + x0.z*a2.z + x0.w*a2.w
                  + x1.x*a3.x + x1.y*a3.y + x1.z*a3.z + x1.w*a3.w;
        float c1b = x0.x*b2.x + x0.y*b2.y + x0.z*b2.z + x0.w*b2.w
                  + x1.x*b3.x + x1.y*b3.y + x1.z*b3.z + x1.w*b3.w;

        float curl0 = fmaf(fr, c0b - c0a, c0a);
        float curl1 = fmaf(fr, c1b - c1a, c1a);
        float curl2 = -(curl0 + curl1);

        atomicAdd(out + 3 * d + 0, curl0);
        atomicAdd(out + 3 * d + 1, curl1);
        atomicAdd(out + 3 * d + 2, curl2);
    }

    // Last consumer block resets state so the next graph replay starts clean.
    __syncthreads();
    if (tid == 0) {
        if (atomicAdd(&g_cdone, 1) == C_TOTAL - 1) {
            g_pdone = 0;
            g_cdone = 0;
            __threadfence();
            atomicExch(&g_flag, 0);
        }
    }
}

extern "C" void kernel_launch(void* const* d_in, const int* in_sizes, int n_in,
                              void* d_out, int out_size) {
    const float* nf   = (const float*)d_in[0];
    const float* pos  = (const float*)d_in[1];
    const int*   esrc = (const int*)  d_in[2];
    const int*   edst = (const int*)  d_in[3];
    const float* W1   = (const float*)d_in[4];
    const float* W2   = (const float*)d_in[5];
    float* out = (float*)d_out;

    fused_kernel<<<GRID, TDIM>>>(nf, pos, esrc, edst, W1, W2, out);
}

// round 4
// speedup vs baseline: 1.7827x; 1.2108x over previous
#include <cuda_runtime.h>
#include <math.h>

constexpr int FIN     = 8;
constexpr int E_TOTAL = 262144;
constexpr int NBASIS  = 10;
constexpr int HID     = 64;
constexpr int WN      = 384;

// Radial table: 16 live difference-functions of r on [0,3], 64B rows.
constexpr int NB = 1024;
__device__ float g_tab[(NB + 1) * 16];
__device__ int g_flag  = 0;
__device__ int g_pdone = 0;
__device__ int g_cdone = 0;

constexpr int TDIM    = 256;
constexpr int GRID    = 512;                   // one wave on 148 SMs @ >=4/SM
constexpr int P_TABLE = 5;                     // 5*256 >= 1025 table points
constexpr int P_ZERO  = 96;                    // 96*256 float4 = 98304 floats
constexpr int P_TOTAL = P_TABLE + P_ZERO;      // 101

// ---------------------------------------------------------------------------
__device__ __forceinline__ void consume_edge(
    int s, int d, float r, float4 x0, float4 x1, float* __restrict__ out)
{
    if (r >= 3.0f) return;                     // w_cut == 0

    float ff = r * ((float)NB / 3.0f);
    int   i  = (int)ff;
    float fr = ff - (float)i;

    const float4* ta = (const float4*)(g_tab + (size_t)i * 16);
    float4 a0 = __ldg(ta + 0), a1 = __ldg(ta + 1);
    float4 a2 = __ldg(ta + 2), a3 = __ldg(ta + 3);
    float4 b0 = __ldg(ta + 4), b1 = __ldg(ta + 5);
    float4 b2 = __ldg(ta + 6), b3 = __ldg(ta + 7);

    float c0a = x0.x*a0.x + x0.y*a0.y + x0.z*a0.z + x0.w*a0.w
              + x1.x*a1.x + x1.y*a1.y + x1.z*a1.z + x1.w*a1.w;
    float c0b = x0.x*b0.x + x0.y*b0.y + x0.z*b0.z + x0.w*b0.w
              + x1.x*b1.x + x1.y*b1.y + x1.z*b1.z + x1.w*b1.w;
    float c1a = x0.x*a2.x + x0.y*a2.y + x0.z*a2.z + x0.w*a2.w
              + x1.x*a3.x + x1.y*a3.y + x1.z*a3.z + x1.w*a3.w;
    float c1b = x0.x*b2.x + x0.y*b2.y + x0.z*b2.z + x0.w*b2.w
              + x1.x*b3.x + x1.y*b3.y + x1.z*b3.z + x1.w*b3.w;

    float curl0 = fmaf(fr, c0b - c0a, c0a);
    float curl1 = fmaf(fr, c1b - c1a, c1a);
    float curl2 = -(curl0 + curl1);

    atomicAdd(out + 3 * d + 0, curl0);
    atomicAdd(out + 3 * d + 1, curl1);
    atomicAdd(out + 3 * d + 2, curl2);
}

__global__ void __launch_bounds__(TDIM, 4)
fused_kernel(const float* __restrict__ nf,
             const float* __restrict__ pos,
             const int*   __restrict__ esrc,
             const int*   __restrict__ edst,
             const float* __restrict__ W1,
             const float* __restrict__ W2,
             float*       __restrict__ out) {
    const int bid = blockIdx.x;
    const int tid = threadIdx.x;

    // ===================== PRODUCER DUTY (first 101 blocks) =================
    if (bid < P_TOTAL) {
        if (bid < P_TABLE) {
            __shared__ float sW1[NBASIS * HID];
            __shared__ float sW2d[HID * 16];    // pre-differenced live W2 cols

            for (int i = tid; i < NBASIS * HID; i += TDIM) sW1[i] = W1[i];
            for (int i = tid; i < HID * 16; i += TDIM) {
                int k = i >> 4, c = i & 15, u = c & 7;
                const float* w = W2 + k * WN + u * 32;
                sW2d[i] = (c < 8) ? (w[2] - w[1]) : (w[0] - w[2]);
            }
            __syncthreads();

            int p = bid * TDIM + tid;
            if (p <= NB) {
                float r = 3.0f * (float)p / (float)NB;

                float emb[NBASIS];
                const float inv_step = 11.0f / 3.0f;
                const float cA = 1.14136f * __expf(2.0f) * sqrtf(10.0f);
                #pragma unroll
                for (int j = 0; j < NBASIS; j++) {
                    float v = 3.0f * (float)(j + 1) / 11.0f;
                    float dd = (r - v) * inv_step;
                    float e = 0.0f;
                    if (fabsf(dd) < 1.0f) {
                        float y = fmaxf(1.0f - dd * dd, 1e-7f);
                        e = cA * __expf(-1.0f / y);
                    }
                    emb[j] = e;
                }

                float acc[16];
                #pragma unroll
                for (int c = 0; c < 16; c++) acc[c] = 0.0f;

                #pragma unroll 4
                for (int k = 0; k < HID; k++) {
                    float s = 0.0f;
                    #pragma unroll
                    for (int j = 0; j < NBASIS; j++)
                        s = fmaf(emb[j], sW1[j * HID + k], s);
                    s *= 0.31622776601683794f;
                    float hk = __fdividef(s, 1.0f + __expf(-s));   // silu
                    #pragma unroll
                    for (int c = 0; c < 16; c++)
                        acc[c] = fmaf(hk, sW2d[k * 16 + c], acc[c]);
                }

                float t    = 10.0f * (1.0f - r * (1.0f / 3.0f));
                float wcut = (t > 0.0f) ? __expf(-1.0f / t) : 0.0f;
                float sc   = wcut * 0.04419417382415922f;  // (1/8)*(1/sqrt8)

                float4* row = (float4*)(g_tab + (size_t)p * 16);
                row[0] = make_float4(acc[0]*sc,  acc[1]*sc,  acc[2]*sc,  acc[3]*sc);
                row[1] = make_float4(acc[4]*sc,  acc[5]*sc,  acc[6]*sc,  acc[7]*sc);
                row[2] = make_float4(acc[8]*sc,  acc[9]*sc,  acc[10]*sc, acc[11]*sc);
                row[3] = make_float4(acc[12]*sc, acc[13]*sc, acc[14]*sc, acc[15]*sc);
            }
        } else {
            int i = (bid - P_TABLE) * TDIM + tid;   // zero output (poisoned)
            ((float4*)out)[i] = make_float4(0.f, 0.f, 0.f, 0.f);
        }
        __threadfence();
        __syncthreads();
        if (tid == 0) {
            if (atomicAdd(&g_pdone, 1) == P_TOTAL - 1)
                atomicExch(&g_flag, 1);
        }
    }

    // ===================== CONSUMER DUTY (all blocks, 2 tiles each) =========
    // Tile 0: prefetch gathers into registers BEFORE waiting on the flag.
    int e0 = bid * TDIM + tid;
    int s0 = __ldg(esrc + e0);
    int d0 = __ldg(edst + e0);
    float dx = __ldg(pos + 3*s0 + 0) - __ldg(pos + 3*d0 + 0);
    float dy = __ldg(pos + 3*s0 + 1) - __ldg(pos + 3*d0 + 1);
    float dz = __ldg(pos + 3*s0 + 2) - __ldg(pos + 3*d0 + 2);
    float r0 = sqrtf(fmaf(dx, dx, fmaf(dy, dy, fmaf(dz, dz, 1e-18f))));
    float4 x0a = make_float4(0.f,0.f,0.f,0.f), x0b = x0a;
    if (r0 < 3.0f) {
        const float4* xp = (const float4*)(nf + (size_t)s0 * FIN);
        x0a = __ldg(xp);
        x0b = __ldg(xp + 1);
    }

    // Wait for table + zeroed output.
    if (tid == 0) {
        volatile int* f = &g_flag;
        while (*f == 0) __nanosleep(64);
    }
    __syncthreads();
    __threadfence();

    consume_edge(s0, d0, r0, x0a, x0b, out);

    // Tile 1: full load + compute (table is ready; latency hidden by MLP).
    {
        int e1 = (bid + GRID) * TDIM + tid;
        int s1 = __ldg(esrc + e1);
        int d1 = __ldg(edst + e1);
        float ex = __ldg(pos + 3*s1 + 0) - __ldg(pos + 3*d1 + 0);
        float ey = __ldg(pos + 3*s1 + 1) - __ldg(pos + 3*d1 + 1);
        float ez = __ldg(pos + 3*s1 + 2) - __ldg(pos + 3*d1 + 2);
        float r1 = sqrtf(fmaf(ex, ex, fmaf(ey, ey, fmaf(ez, ez, 1e-18f))));
        float4 x1a = make_float4(0.f,0.f,0.f,0.f), x1b = x1a;
        if (r1 < 3.0f) {
            const float4* xp = (const float4*)(nf + (size_t)s1 * FIN);
            x1a = __ldg(xp);
            x1b = __ldg(xp + 1);
        }
        consume_edge(s1, d1, r1, x1a, x1b, out);
    }

    // Last block resets the flags so the next graph replay starts clean.
    __syncthreads();
    if (tid == 0) {
        if (atomicAdd(&g_cdone, 1) == GRID - 1) {
            g_pdone = 0;
            g_cdone = 0;
            __threadfence();
            atomicExch(&g_flag, 0);
        }
    }
}

extern "C" void kernel_launch(void* const* d_in, const int* in_sizes, int n_in,
                              void* d_out, int out_size) {
    const float* nf   = (const float*)d_in[0];
    const float* pos  = (const float*)d_in[1];
    const int*   esrc = (const int*)  d_in[2];
    const int*   edst = (const int*)  d_in[3];
    const float* W1   = (const float*)d_in[4];
    const float* W2   = (const float*)d_in[5];
    float* out = (float*)d_out;

    fused_kernel<<<GRID, TDIM>>>(nf, pos, esrc, edst, W1, W2, out);
}

// round 5
// speedup vs baseline: 1.9151x; 1.0743x over previous
#include <cuda_runtime.h>
#include <math.h>

constexpr int FIN     = 8;
constexpr int E_TOTAL = 262144;
constexpr int NBASIS  = 10;
constexpr int HID     = 64;
constexpr int WN      = 384;
constexpr int NNODES  = 32768;

// Radial table: 16 live difference-functions of r on [0,3], 64B rows.
constexpr int NB         = 1024;
constexpr int TAB_FLOATS = (NB + 1) * 16;     // 16400
constexpr int TAB_F4     = TAB_FLOATS / 4;    // 4100
constexpr int TAB_BYTES  = TAB_FLOATS * 4;    // 65600

__device__ float  g_tab[TAB_FLOATS];          // zero at load; re-zeroed at reset
__device__ float4 g_pos4[NNODES];             // padded positions
__device__ int g_flag  = 0;
__device__ int g_pdone = 0;
__device__ int g_cdone = 0;

constexpr int TDIM   = 512;
constexpr int GRID   = 256;                   // 2 blocks/SM -> one wave
constexpr int EPB    = E_TOTAL / GRID;        // 1024 edges per block (2 tiles)

// Producer partition (all producer blocks are also consumers afterwards)
constexpr int KCHUNK   = 16;
constexpr int NCHUNK   = HID / KCHUNK;        // 4
constexpr int PBLK     = 3;                   // 3*512 >= 1025 table points
constexpr int T_BLOCKS = NCHUNK * PBLK;       // 12
constexpr int Z_BLOCKS = 48;                  // 48*512 float4 = 24576 = out/4
constexpr int P4_BLOCKS= 64;                  // 64*512 = 32768 nodes
constexpr int P_TOTAL  = T_BLOCKS + Z_BLOCKS + P4_BLOCKS;   // 124

// ---------------------------------------------------------------------------
__device__ __forceinline__ void edge_compute(
    const float* __restrict__ s_tab, int d, float r,
    float4 x0, float4 x1, float* __restrict__ out)
{
    if (r >= 3.0f) return;                    // w_cut == 0

    float ff = r * ((float)NB / 3.0f);
    int   i  = (int)ff;
    float fr = ff - (float)i;

    const float4* ta = (const float4*)(s_tab + i * 16);   // LDS.128 x8
    float4 a0 = ta[0], a1 = ta[1], a2 = ta[2], a3 = ta[3];
    float4 b0 = ta[4], b1 = ta[5], b2 = ta[6], b3 = ta[7];

    float c0a = x0.x*a0.x + x0.y*a0.y + x0.z*a0.z + x0.w*a0.w
              + x1.x*a1.x + x1.y*a1.y + x1.z*a1.z + x1.w*a1.w;
    float c1a = x0.x*a2.x + x0.y*a2.y + x0.z*a2.z + x0.w*a2.w
              + x1.x*a3.x + x1.y*a3.y + x1.z*a3.z + x1.w*a3.w;
    float c0b = x0.x*b0.x + x0.y*b0.y + x0.z*b0.z + x0.w*b0.w
              + x1.x*b1.x + x1.y*b1.y + x1.z*b1.z + x1.w*b1.w;
    float c1b = x0.x*b2.x + x0.y*b2.y + x0.z*b2.z + x0.w*b2.w
              + x1.x*b3.x + x1.y*b3.y + x1.z*b3.z + x1.w*b3.w;

    float curl0 = fmaf(fr, c0b - c0a, c0a);
    float curl1 = fmaf(fr, c1b - c1a, c1a);
    float curl2 = -(curl0 + curl1);

    atomicAdd(out + 3 * d + 0, curl0);
    atomicAdd(out + 3 * d + 1, curl1);
    atomicAdd(out + 3 * d + 2, curl2);
}

// ---------------------------------------------------------------------------
__global__ void __launch_bounds__(TDIM, 2)
fused_kernel(const float* __restrict__ nf,
             const float* __restrict__ pos,
             const int*   __restrict__ esrc,
             const int*   __restrict__ edst,
             const float* __restrict__ W1,
             const float* __restrict__ W2,
             float*       __restrict__ out) {
    extern __shared__ float s_tab[];          // 65600 B
    const int bid = blockIdx.x;
    const int tid = threadIdx.x;

    // ===================== PRODUCER DUTY =====================
    if (bid < P_TOTAL) {
        if (bid < T_BLOCKS) {
            // ---- radial table, k-chunk partial sums ----
            const int chunk = bid / PBLK;               // 0..3
            const int pblk  = bid % PBLK;               // 0..2
            const int k0    = chunk * KCHUNK;

            // scratch in dynamic smem (overwritten later by table copy)
            float* sW1  = s_tab;                        // 640 floats
            float* sW2d = s_tab + 640;                  // 256 floats

            for (int i = tid; i < NBASIS * HID; i += TDIM) sW1[i] = W1[i];
            for (int i = tid; i < KCHUNK * 16; i += TDIM) {
                int kk = i >> 4, c = i & 15, u = c & 7;
                const float* w = W2 + (k0 + kk) * WN + u * 32;
                sW2d[i] = (c < 8) ? (w[2] - w[1]) : (w[0] - w[2]);
            }
            __syncthreads();

            int p = pblk * TDIM + tid;
            if (p <= NB) {
                float r = 3.0f * (float)p / (float)NB;

                float emb[NBASIS];
                const float inv_step = 11.0f / 3.0f;
                const float cA = 1.14136f * __expf(2.0f) * sqrtf(10.0f);
                #pragma unroll
                for (int j = 0; j < NBASIS; j++) {
                    float v  = 3.0f * (float)(j + 1) / 11.0f;
                    float dd = (r - v) * inv_step;
                    float e  = 0.0f;
                    if (fabsf(dd) < 1.0f) {
                        float y = fmaxf(1.0f - dd * dd, 1e-7f);
                        e = cA * __expf(-1.0f / y);
                    }
                    emb[j] = e;
                }

                float acc[16];
                #pragma unroll
                for (int c = 0; c < 16; c++) acc[c] = 0.0f;

                #pragma unroll
                for (int kk = 0; kk < KCHUNK; kk++) {
                    float s = 0.0f;
                    #pragma unroll
                    for (int j = 0; j < NBASIS; j++)
                        s = fmaf(emb[j], sW1[j * HID + k0 + kk], s);
                    s *= 0.31622776601683794f;                   // 1/sqrt(10)
                    float hk = __fdividef(s, 1.0f + __expf(-s)); // silu
                    #pragma unroll
                    for (int c = 0; c < 16; c++)
                        acc[c] = fmaf(hk, sW2d[kk * 16 + c], acc[c]);
                }

                float t    = 10.0f * (1.0f - r * (1.0f / 3.0f));
                float wcut = (t > 0.0f) ? __expf(-1.0f / t) : 0.0f;
                float sc   = wcut * 0.04419417382415922f;  // (1/8)*(1/sqrt8)

                #pragma unroll
                for (int c = 0; c < 16; c++)
                    atomicAdd(&g_tab[p * 16 + c], acc[c] * sc);
            }
            __syncthreads();   // smem scratch reuse barrier
        } else if (bid < T_BLOCKS + Z_BLOCKS) {
            // ---- zero the output (harness poisons it) ----
            int i = (bid - T_BLOCKS) * TDIM + tid;
            ((float4*)out)[i] = make_float4(0.f, 0.f, 0.f, 0.f);
        } else {
            // ---- pad positions into float4 scratch ----
            int n = (bid - T_BLOCKS - Z_BLOCKS) * TDIM + tid;
            g_pos4[n] = make_float4(pos[3*n], pos[3*n+1], pos[3*n+2], 0.f);
        }
        __threadfence();
        __syncthreads();
        if (tid == 0) {
            if (atomicAdd(&g_pdone, 1) == P_TOTAL - 1)
                atomicExch(&g_flag, 1);
        }
    }

    // ===================== CONSUMER DUTY (2 tiles of 512 edges) =============
    // Tile 0: prefetch via RAW pos (independent of producers) before the spin.
    const int ebase = bid * EPB;
    int s0 = __ldg(esrc + ebase + tid);
    int d0 = __ldg(edst + ebase + tid);
    float dx = __ldg(pos + 3*s0 + 0) - __ldg(pos + 3*d0 + 0);
    float dy = __ldg(pos + 3*s0 + 1) - __ldg(pos + 3*d0 + 1);
    float dz = __ldg(pos + 3*s0 + 2) - __ldg(pos + 3*d0 + 2);
    float r0 = sqrtf(fmaf(dx, dx, fmaf(dy, dy, fmaf(dz, dz, 1e-18f))));
    float4 x0a = make_float4(0.f,0.f,0.f,0.f), x0b = x0a;
    if (r0 < 3.0f) {
        const float4* xp = (const float4*)(nf + (size_t)s0 * FIN);
        x0a = __ldg(xp);
        x0b = __ldg(xp + 1);
    }
    int s1 = __ldg(esrc + ebase + TDIM + tid);
    int d1 = __ldg(edst + ebase + TDIM + tid);

    // Wait for producers.
    if (tid == 0) {
        volatile int* f = &g_flag;
        while (*f == 0) __nanosleep(64);
    }
    __syncthreads();
    __threadfence();

    // Copy table into shared memory (coalesced).
    {
        float4* st4 = (float4*)s_tab;
        const float4* gt4 = (const float4*)g_tab;
        for (int i = tid; i < TAB_F4; i += TDIM) st4[i] = __ldg(gt4 + i);
    }
    __syncthreads();

    edge_compute(s_tab, d0, r0, x0a, x0b, out);

    // Tile 1: uses padded pos4.
    {
        float4 ps = __ldg(g_pos4 + s1);
        float4 pd = __ldg(g_pos4 + d1);
        float ex = ps.x - pd.x, ey = ps.y - pd.y, ez = ps.z - pd.z;
        float r1 = sqrtf(fmaf(ex, ex, fmaf(ey, ey, fmaf(ez, ez, 1e-18f))));
        float4 x1a = make_float4(0.f,0.f,0.f,0.f), x1b = x1a;
        if (r1 < 3.0f) {
            const float4* xp = (const float4*)(nf + (size_t)s1 * FIN);
            x1a = __ldg(xp);
            x1b = __ldg(xp + 1);
        }
        edge_compute(s_tab, d1, r1, x1a, x1b, out);
    }

    // ---- last block resets global state for the next graph replay ----
    __shared__ int s_last;
    __syncthreads();
    if (tid == 0) s_last = (atomicAdd(&g_cdone, 1) == GRID - 1) ? 1 : 0;
    __syncthreads();
    if (s_last) {
        float4* gt4 = (float4*)g_tab;
        for (int i = tid; i < TAB_F4; i += TDIM)
            gt4[i] = make_float4(0.f, 0.f, 0.f, 0.f);
        __threadfence();
        __syncthreads();
        if (tid == 0) {
            g_pdone = 0;
            g_cdone = 0;
            __threadfence();
            atomicExch(&g_flag, 0);
        }
    }
}

// ---------------------------------------------------------------------------
extern "C" void kernel_launch(void* const* d_in, const int* in_sizes, int n_in,
                              void* d_out, int out_size) {
    const float* nf   = (const float*)d_in[0];
    const float* pos  = (const float*)d_in[1];
    const int*   esrc = (const int*)  d_in[2];
    const int*   edst = (const int*)  d_in[3];
    const float* W1   = (const float*)d_in[4];
    const float* W2   = (const float*)d_in[5];
    float* out = (float*)d_out;

    static int configured = 0;
    if (!configured) {
        cudaFuncSetAttribute(fused_kernel,
                             cudaFuncAttributeMaxDynamicSharedMemorySize,
                             TAB_BYTES);
        configured = 1;
    }
    fused_kernel<<<GRID, TDIM, TAB_BYTES>>>(nf, pos, esrc, edst, W1, W2, out);
}

// round 6
// speedup vs baseline: 2.7432x; 1.4324x over previous
#include <cuda_runtime.h>
#include <cuda_fp16.h>
#include <math.h>

constexpr int FIN     = 8;
constexpr int E_TOTAL = 262144;
constexpr int NBASIS  = 10;
constexpr int HID     = 64;
constexpr int WN      = 384;
constexpr int NNODES  = 32768;

// Radial table: 16 live difference-functions of r on [0,3], fp16, 32B rows.
// Row p: h[0..7] = c0[u] = g_{u,2}-g_{u,1}; h[8..15] = c1[u] = g_{u,0}-g_{u,2}.
// curl0 = x.c0, curl1 = x.c1, curl2 = -(curl0+curl1). Rows i,i+1 = 64B contig.
constexpr int NB = 2048;
__device__ __half  g_tab_h[(NB + 1) * 16];
__device__ float4  g_pos4[NNODES];

// ---------------------------------------------------------------------------
// Setup kernel: role-split blocks build the fp16 table, zero the (poisoned)
// output, and pad pos into float4.
// ---------------------------------------------------------------------------
constexpr int STD       = 256;
constexpr int T_BLOCKS  = 9;     // 9*256 = 2304 >= 2049 table points
constexpr int Z_BLOCKS  = 96;    // 96*256 float4 = 98304 floats = out
constexpr int P4_BLOCKS = 128;   // 128*256 = 32768 nodes
constexpr int S_GRID    = T_BLOCKS + Z_BLOCKS + P4_BLOCKS;   // 233

__global__ void __launch_bounds__(STD)
setup_kernel(const float* __restrict__ pos,
             const float* __restrict__ W1,
             const float* __restrict__ W2,
             float* __restrict__ out) {
    const int bid = blockIdx.x;
    const int tid = threadIdx.x;

    if (bid < T_BLOCKS) {
        __shared__ float sW1[NBASIS * HID];   // 640
        __shared__ float sW2d[HID * 16];      // pre-differenced live W2 cols

        for (int i = tid; i < NBASIS * HID; i += STD) sW1[i] = W1[i];
        for (int i = tid; i < HID * 16; i += STD) {
            int k = i >> 4, c = i & 15, u = c & 7;
            const float* w = W2 + k * WN + u * 32;
            sW2d[i] = (c < 8) ? (w[2] - w[1]) : (w[0] - w[2]);
        }
        __syncthreads();

        int p = bid * STD + tid;
        if (p <= NB) {
            float r = 3.0f * (float)p / (float)NB;

            float emb[NBASIS];
            const float inv_step = 11.0f / 3.0f;
            const float cA = 1.14136f * __expf(2.0f) * sqrtf(10.0f);
            #pragma unroll
            for (int j = 0; j < NBASIS; j++) {
                float v  = 3.0f * (float)(j + 1) / 11.0f;
                float dd = (r - v) * inv_step;
                float e  = 0.0f;
                if (fabsf(dd) < 1.0f) {
                    float y = fmaxf(1.0f - dd * dd, 1e-7f);
                    e = cA * __expf(-1.0f / y);
                }
                emb[j] = e;
            }

            float acc[16];
            #pragma unroll
            for (int c = 0; c < 16; c++) acc[c] = 0.0f;

            #pragma unroll 4
            for (int k = 0; k < HID; k++) {
                float s = 0.0f;
                #pragma unroll
                for (int j = 0; j < NBASIS; j++)
                    s = fmaf(emb[j], sW1[j * HID + k], s);
                s *= 0.31622776601683794f;                    // 1/sqrt(10)
                float hk = __fdividef(s, 1.0f + __expf(-s));  // silu
                #pragma unroll
                for (int c = 0; c < 16; c++)
                    acc[c] = fmaf(hk, sW2d[k * 16 + c], acc[c]);
            }

            float t    = 10.0f * (1.0f - r * (1.0f / 3.0f));
            float wcut = (t > 0.0f) ? __expf(-1.0f / t) : 0.0f;
            float sc   = wcut * 0.04419417382415922f;   // (1/8)*(1/sqrt8)

            __half2* row = (__half2*)(g_tab_h + (size_t)p * 16);
            #pragma unroll
            for (int c = 0; c < 8; c++)
                row[c] = __floats2half2_rn(acc[2*c] * sc, acc[2*c+1] * sc);
        }
    } else if (bid < T_BLOCKS + Z_BLOCKS) {
        int i = (bid - T_BLOCKS) * STD + tid;         // zero poisoned output
        ((float4*)out)[i] = make_float4(0.f, 0.f, 0.f, 0.f);
    } else {
        int n = (bid - T_BLOCKS - Z_BLOCKS) * STD + tid;
        g_pos4[n] = make_float4(__ldg(pos + 3*n), __ldg(pos + 3*n + 1),
                                __ldg(pos + 3*n + 2), 0.f);
    }
}

// ---------------------------------------------------------------------------
// Edge kernel: 1 edge/thread; fp16 table lerp via L1; direct curl scatter.
// ---------------------------------------------------------------------------
__device__ __forceinline__ float dot8h(uint4 rw, float4 x0, float4 x1) {
    float2 p0 = __half22float2(*(__half2*)&rw.x);
    float2 p1 = __half22float2(*(__half2*)&rw.y);
    float2 p2 = __half22float2(*(__half2*)&rw.z);
    float2 p3 = __half22float2(*(__half2*)&rw.w);
    return x0.x*p0.x + x0.y*p0.y + x0.z*p1.x + x0.w*p1.y
         + x1.x*p2.x + x1.y*p2.y + x1.z*p3.x + x1.w*p3.y;
}

__global__ void __launch_bounds__(256, 6)
edge_kernel(const float* __restrict__ nf,
            const int*   __restrict__ esrc,
            const int*   __restrict__ edst,
            float*       __restrict__ out) {
    int e = blockIdx.x * 256 + threadIdx.x;

    int s = __ldg(esrc + e);
    int d = __ldg(edst + e);

    float4 ps = __ldg(g_pos4 + s);
    float4 pd = __ldg(g_pos4 + d);
    float dx = ps.x - pd.x, dy = ps.y - pd.y, dz = ps.z - pd.z;
    float r  = sqrtf(fmaf(dx, dx, fmaf(dy, dy, fmaf(dz, dz, 1e-18f))));

    if (r >= 3.0f) return;                    // w_cut == 0

    float ff = r * ((float)NB / 3.0f);
    int   i  = (int)ff;
    float fr = ff - (float)i;

    const float4* xp = (const float4*)(nf + (size_t)s * FIN);
    float4 x0 = __ldg(xp);
    float4 x1 = __ldg(xp + 1);

    const uint4* tp = (const uint4*)(g_tab_h + (size_t)i * 16);
    uint4 ra = __ldg(tp + 0);   // c0, row i
    uint4 rb = __ldg(tp + 1);   // c1, row i
    uint4 rc = __ldg(tp + 2);   // c0, row i+1
    uint4 rd = __ldg(tp + 3);   // c1, row i+1

    float c0a = dot8h(ra, x0, x1);
    float c1a = dot8h(rb, x0, x1);
    float c0b = dot8h(rc, x0, x1);
    float c1b = dot8h(rd, x0, x1);

    float curl0 = fmaf(fr, c0b - c0a, c0a);
    float curl1 = fmaf(fr, c1b - c1a, c1a);
    float curl2 = -(curl0 + curl1);

    atomicAdd(out + 3 * d + 0, curl0);
    atomicAdd(out + 3 * d + 1, curl1);
    atomicAdd(out + 3 * d + 2, curl2);
}

// ---------------------------------------------------------------------------
extern "C" void kernel_launch(void* const* d_in, const int* in_sizes, int n_in,
                              void* d_out, int out_size) {
    const float* nf   = (const float*)d_in[0];
    const float* pos  = (const float*)d_in[1];
    const int*   esrc = (const int*)  d_in[2];
    const int*   edst = (const int*)  d_in[3];
    const float* W1   = (const float*)d_in[4];
    const float* W2   = (const float*)d_in[5];
    float* out = (float*)d_out;

    setup_kernel<<<S_GRID, STD>>>(pos, W1, W2, out);
    edge_kernel<<<E_TOTAL / 256, 256>>>(nf, esrc, edst, out);
}